// round 2
// baseline (speedup 1.0000x reference)
#include <cuda_runtime.h>

#define EPS 1e-5f
#define C_DIM 64
#define B_DIM 8
#define CTX_DIM 256

// Fused modulation coefficients: [0..511]   = A[b][c] = gamma[c]*(1+scale[b][c])
//                                [512..1023]= B[b][c] = beta[c]*(1+scale[b][c]) + shift[b][c]
__device__ float g_coef[2 * B_DIM * C_DIM];

// ---------------------------------------------------------------------------
// Kernel A: tiny MLP  h = silu(token) @ W^T + b,  then fuse coefficients.
// One block, 256 threads. 8*128*256 = 262K MACs — negligible.
// ---------------------------------------------------------------------------
__global__ void mlp_coef_kernel(const float* __restrict__ token,  // [8,256]
                                const float* __restrict__ W,      // [128,256]
                                const float* __restrict__ bvec,   // [128]
                                const float* __restrict__ gamma,  // [64]
                                const float* __restrict__ beta)   // [64]
{
    __shared__ float st[B_DIM * CTX_DIM];   // silu(token), 8 KB
    __shared__ float h[B_DIM * 2 * C_DIM];  // 8x128, 4 KB
    const int tid = threadIdx.x;

    for (int i = tid; i < B_DIM * CTX_DIM; i += blockDim.x) {
        float v = token[i];
        st[i] = v / (1.0f + expf(-v));
    }
    __syncthreads();

    for (int i = tid; i < B_DIM * 2 * C_DIM; i += blockDim.x) {
        const int j = i / (2 * C_DIM);
        const int o = i % (2 * C_DIM);
        float acc = bvec[o];
        const float* srow = st + j * CTX_DIM;
        const float* wrow = W + o * CTX_DIM;
#pragma unroll 8
        for (int k = 0; k < CTX_DIM; ++k) acc += srow[k] * wrow[k];
        h[i] = acc;
    }
    __syncthreads();

    for (int i = tid; i < B_DIM * C_DIM; i += blockDim.x) {
        const int j = i / C_DIM;
        const int c = i % C_DIM;
        const float shift = h[j * 2 * C_DIM + c];
        const float scale = h[j * 2 * C_DIM + C_DIM + c];
        g_coef[i] = gamma[c] * (1.0f + scale);
        g_coef[B_DIM * C_DIM + i] = beta[c] * (1.0f + scale) + shift;
    }
}

// ---------------------------------------------------------------------------
// Kernel B: LayerNorm(C=64) + modulation.
// Half-warp (16 lanes) per row, float4 per lane -> 64 floats, fully coalesced.
// 256 threads/block -> 16 rows/block.
// ---------------------------------------------------------------------------
__global__ void __launch_bounds__(256)
norm_mod_kernel(const float* __restrict__ x,
                const int* __restrict__ coors,   // [N,4] int32, col 0 = batch
                float* __restrict__ out,
                int n_rows)
{
    __shared__ float sA[B_DIM * C_DIM];
    __shared__ float sB[B_DIM * C_DIM];

    const int tid = threadIdx.x;
    for (int i = tid; i < B_DIM * C_DIM; i += 256) {
        sA[i] = g_coef[i];
        sB[i] = g_coef[B_DIM * C_DIM + i];
    }
    __syncthreads();

    const int warp = tid >> 5;
    const int lane = tid & 31;
    const int half = lane >> 4;   // which row within the warp
    const int sub  = lane & 15;   // lane within the half-warp

    const long long row = ((long long)blockIdx.x * 8 + warp) * 2 + half;
    if (row >= n_rows) return;

    const float4 v = reinterpret_cast<const float4*>(x + row * C_DIM)[sub];

    float s  = v.x + v.y + v.z + v.w;
    float s2 = v.x * v.x + v.y * v.y + v.z * v.z + v.w * v.w;
#pragma unroll
    for (int o = 8; o >= 1; o >>= 1) {
        s  += __shfl_xor_sync(0xffffffffu, s,  o);
        s2 += __shfl_xor_sync(0xffffffffu, s2, o);
    }

    const float mu  = s * (1.0f / 64.0f);
    const float var = s2 * (1.0f / 64.0f) - mu * mu;
    const float rs  = rsqrtf(var + EPS);

    const int b = coors[row * 4];
    const float4 a4 = reinterpret_cast<const float4*>(sA + b * C_DIM)[sub];
    const float4 b4 = reinterpret_cast<const float4*>(sB + b * C_DIM)[sub];

    float4 o4;
    o4.x = (v.x - mu) * rs * a4.x + b4.x;
    o4.y = (v.y - mu) * rs * a4.y + b4.y;
    o4.z = (v.z - mu) * rs * a4.z + b4.z;
    o4.w = (v.w - mu) * rs * a4.w + b4.w;

    reinterpret_cast<float4*>(out + row * C_DIM)[sub] = o4;
}

// ---------------------------------------------------------------------------
// Launch. Inputs (metadata order): x, dataset_token, gamma, beta, W, b, coors
// ---------------------------------------------------------------------------
extern "C" void kernel_launch(void* const* d_in, const int* in_sizes, int n_in,
                              void* d_out, int out_size)
{
    const float* x      = (const float*)d_in[0];
    const float* token  = (const float*)d_in[1];
    const float* gamma  = (const float*)d_in[2];
    const float* beta   = (const float*)d_in[3];
    const float* W      = (const float*)d_in[4];
    const float* bvec   = (const float*)d_in[5];
    const int*   coors  = (const int*)d_in[6];
    float* out = (float*)d_out;

    const int n_rows = in_sizes[0] / C_DIM;

    mlp_coef_kernel<<<1, 256>>>(token, W, bvec, gamma, beta);

    const int rows_per_block = 16;
    const int grid = (n_rows + rows_per_block - 1) / rows_per_block;
    norm_mod_kernel<<<grid, 256>>>(x, coors, out, n_rows);
}

// round 3
// speedup vs baseline: 2.6662x; 2.6662x over previous
#include <cuda_runtime.h>

#define EPS 1e-5f
#define C_DIM 64
#define B_DIM 8
#define CTX_DIM 256

// Fused modulation coefficients: [0..511]   = A[b][c] = gamma[c]*(1+scale[b][c])
//                                [512..1023]= B[b][c] = beta[c]*(1+scale[b][c]) + shift[b][c]
__device__ float g_coef[2 * B_DIM * C_DIM];

// ---------------------------------------------------------------------------
// Kernel A: tiny MLP, fully parallel. One warp per (j, c) pair: 8*64 = 512
// warps = 64 blocks x 256 threads. Each warp computes BOTH dot products
// (shift = W[c] . silu(token[j]),  scale = W[64+c] . silu(token[j]))
// and writes the fused A/B coefficients.
// ---------------------------------------------------------------------------
__global__ void __launch_bounds__(256)
mlp_coef_kernel(const float* __restrict__ token,  // [8,256]
                const float* __restrict__ W,      // [128,256]
                const float* __restrict__ bvec,   // [128]
                const float* __restrict__ gamma,  // [64]
                const float* __restrict__ beta)   // [64]
{
    const int wg   = blockIdx.x * 8 + (threadIdx.x >> 5);  // 0..511
    const int lane = threadIdx.x & 31;
    const int j = wg >> 6;       // batch 0..7
    const int c = wg & 63;       // channel 0..63

    const float* trow = token + j * CTX_DIM;
    const float* wsh  = W + c * CTX_DIM;
    const float* wsc  = W + (C_DIM + c) * CTX_DIM;

    float acc_sh = 0.0f, acc_sc = 0.0f;
#pragma unroll
    for (int i = 0; i < 8; ++i) {
        const int k = lane + 32 * i;
        const float v = trow[k];
        const float s = v / (1.0f + expf(-v));
        acc_sh += s * wsh[k];
        acc_sc += s * wsc[k];
    }
#pragma unroll
    for (int o = 16; o >= 1; o >>= 1) {
        acc_sh += __shfl_xor_sync(0xffffffffu, acc_sh, o);
        acc_sc += __shfl_xor_sync(0xffffffffu, acc_sc, o);
    }

    if (lane == 0) {
        const float shift = acc_sh + bvec[c];
        const float scale = acc_sc + bvec[C_DIM + c];
        g_coef[j * C_DIM + c]                   = gamma[c] * (1.0f + scale);
        g_coef[B_DIM * C_DIM + j * C_DIM + c]   = beta[c] * (1.0f + scale) + shift;
    }
}

// ---------------------------------------------------------------------------
// Kernel B: LayerNorm(C=64) + modulation.
// Half-warp (16 lanes) per row, float4 per lane. Each thread handles TWO
// rows (row and row+2) for ILP. Block of 256 threads covers 32 rows.
// ---------------------------------------------------------------------------
__global__ void __launch_bounds__(256)
norm_mod_kernel(const float* __restrict__ x,
                const int* __restrict__ coors,   // [N,4] int32, col 0 = batch
                float* __restrict__ out,
                int n_rows)
{
    __shared__ float sA[B_DIM * C_DIM];
    __shared__ float sB[B_DIM * C_DIM];

    const int tid = threadIdx.x;
    for (int i = tid; i < B_DIM * C_DIM; i += 256) {
        sA[i] = g_coef[i];
        sB[i] = g_coef[B_DIM * C_DIM + i];
    }
    __syncthreads();

    const int warp = tid >> 5;
    const int lane = tid & 31;
    const int half = lane >> 4;   // row parity within the warp
    const int sub  = lane & 15;   // lane within the half-warp

    // Block covers 32 consecutive rows; warp w covers rows 4w..4w+3.
    const long long base = (long long)blockIdx.x * 32 + warp * 4 + half;
    const long long rowA = base;       // rows 4w+0 / 4w+1
    const long long rowB = base + 2;   // rows 4w+2 / 4w+3

    const bool okA = rowA < n_rows;
    const bool okB = rowB < n_rows;

    float4 va = okA ? __ldcs(reinterpret_cast<const float4*>(x + rowA * C_DIM) + sub)
                    : make_float4(0.f, 0.f, 0.f, 0.f);
    float4 vb = okB ? __ldcs(reinterpret_cast<const float4*>(x + rowB * C_DIM) + sub)
                    : make_float4(0.f, 0.f, 0.f, 0.f);

    float sa  = va.x + va.y + va.z + va.w;
    float sa2 = va.x * va.x + va.y * va.y + va.z * va.z + va.w * va.w;
    float sb  = vb.x + vb.y + vb.z + vb.w;
    float sb2 = vb.x * vb.x + vb.y * vb.y + vb.z * vb.z + vb.w * vb.w;

#pragma unroll
    for (int o = 8; o >= 1; o >>= 1) {
        sa  += __shfl_xor_sync(0xffffffffu, sa,  o);
        sa2 += __shfl_xor_sync(0xffffffffu, sa2, o);
        sb  += __shfl_xor_sync(0xffffffffu, sb,  o);
        sb2 += __shfl_xor_sync(0xffffffffu, sb2, o);
    }

    if (okA) {
        const float mu  = sa * (1.0f / 64.0f);
        const float var = sa2 * (1.0f / 64.0f) - mu * mu;
        const float rs  = rsqrtf(var + EPS);
        const int b = coors[rowA * 4];
        const float4 a4 = reinterpret_cast<const float4*>(sA + b * C_DIM)[sub];
        const float4 b4 = reinterpret_cast<const float4*>(sB + b * C_DIM)[sub];
        float4 o4;
        o4.x = (va.x - mu) * rs * a4.x + b4.x;
        o4.y = (va.y - mu) * rs * a4.y + b4.y;
        o4.z = (va.z - mu) * rs * a4.z + b4.z;
        o4.w = (va.w - mu) * rs * a4.w + b4.w;
        __stcs(reinterpret_cast<float4*>(out + rowA * C_DIM) + sub, o4);
    }
    if (okB) {
        const float mu  = sb * (1.0f / 64.0f);
        const float var = sb2 * (1.0f / 64.0f) - mu * mu;
        const float rs  = rsqrtf(var + EPS);
        const int b = coors[rowB * 4];
        const float4 a4 = reinterpret_cast<const float4*>(sA + b * C_DIM)[sub];
        const float4 b4 = reinterpret_cast<const float4*>(sB + b * C_DIM)[sub];
        float4 o4;
        o4.x = (vb.x - mu) * rs * a4.x + b4.x;
        o4.y = (vb.y - mu) * rs * a4.y + b4.y;
        o4.z = (vb.z - mu) * rs * a4.z + b4.z;
        o4.w = (vb.w - mu) * rs * a4.w + b4.w;
        __stcs(reinterpret_cast<float4*>(out + rowB * C_DIM) + sub, o4);
    }
}

// ---------------------------------------------------------------------------
// Launch. Inputs (metadata order): x, dataset_token, gamma, beta, W, b, coors
// ---------------------------------------------------------------------------
extern "C" void kernel_launch(void* const* d_in, const int* in_sizes, int n_in,
                              void* d_out, int out_size)
{
    const float* x      = (const float*)d_in[0];
    const float* token  = (const float*)d_in[1];
    const float* gamma  = (const float*)d_in[2];
    const float* beta   = (const float*)d_in[3];
    const float* W      = (const float*)d_in[4];
    const float* bvec   = (const float*)d_in[5];
    const int*   coors  = (const int*)d_in[6];
    float* out = (float*)d_out;

    const int n_rows = in_sizes[0] / C_DIM;

    mlp_coef_kernel<<<64, 256>>>(token, W, bvec, gamma, beta);

    const int rows_per_block = 32;
    const int grid = (n_rows + rows_per_block - 1) / rows_per_block;
    norm_mod_kernel<<<grid, 256>>>(x, coors, out, n_rows);
}

// round 4
// speedup vs baseline: 2.7416x; 1.0283x over previous
#include <cuda_runtime.h>

#define EPS 1e-5f
#define C_DIM 64
#define B_DIM 8
#define CTX_DIM 256

// Fused modulation coefficients: [0..511]   = A[b][c] = gamma[c]*(1+scale[b][c])
//                                [512..1023]= B[b][c] = beta[c]*(1+scale[b][c]) + shift[b][c]
__device__ float g_coef[2 * B_DIM * C_DIM];
// g_bound[k] = first row index whose batch >= k+1 (k = 0..6). batch(row) = #{k : bound[k] <= row}
__device__ int g_bound[B_DIM - 1];

// ---------------------------------------------------------------------------
// Setup kernel (one launch): blocks 0..63 run the tiny MLP (one warp per
// (batch, channel) pair, fused A/B coefficients). Block 64 computes the 7
// batch boundaries from the SORTED coors[:,0] column using a warp-parallel
// 33-way search (4 rounds of 32 concurrent probes).
// ---------------------------------------------------------------------------
__global__ void __launch_bounds__(256)
setup_kernel(const float* __restrict__ token,  // [8,256]
             const float* __restrict__ W,      // [128,256]
             const float* __restrict__ bvec,   // [128]
             const float* __restrict__ gamma,  // [64]
             const float* __restrict__ beta,   // [64]
             const int* __restrict__ coors,    // [N,4] int32, col 0 sorted
             int n_rows)
{
    const int warp = threadIdx.x >> 5;
    const int lane = threadIdx.x & 31;

    if (blockIdx.x < 64) {
        // ---- MLP: warp wg handles (j, c) ----
        const int wg = blockIdx.x * 8 + warp;   // 0..511
        const int j = wg >> 6;                  // batch 0..7
        const int c = wg & 63;                  // channel 0..63

        const float* trow = token + j * CTX_DIM;
        const float* wsh  = W + c * CTX_DIM;
        const float* wsc  = W + (C_DIM + c) * CTX_DIM;

        float acc_sh = 0.0f, acc_sc = 0.0f;
#pragma unroll
        for (int i = 0; i < 8; ++i) {
            const int k = lane + 32 * i;
            const float v = trow[k];
            const float s = v / (1.0f + expf(-v));
            acc_sh += s * wsh[k];
            acc_sc += s * wsc[k];
        }
#pragma unroll
        for (int o = 16; o >= 1; o >>= 1) {
            acc_sh += __shfl_xor_sync(0xffffffffu, acc_sh, o);
            acc_sc += __shfl_xor_sync(0xffffffffu, acc_sc, o);
        }
        if (lane == 0) {
            const float shift = acc_sh + bvec[c];
            const float scale = acc_sc + bvec[C_DIM + c];
            g_coef[j * C_DIM + c]                 = gamma[c] * (1.0f + scale);
            g_coef[B_DIM * C_DIM + j * C_DIM + c] = beta[c] * (1.0f + scale) + shift;
        }
    } else {
        // ---- Boundary search: warps 0..6 find lower_bound(batch >= k) ----
        if (warp >= B_DIM - 1) return;
        const int k = warp + 1;
        int lo = 0, hi = n_rows;   // answer in [lo, hi]; batch[lo-1] < k

        while (hi - lo > 32) {
            const long long len = hi - lo;
            const int pos = lo + (int)(((long long)(lane + 1) * len) / 33);
            const bool ge = __ldg(coors + (long long)pos * 4) >= k;
            const unsigned m = __ballot_sync(0xffffffffu, ge);
            if (m == 0) {
                lo = lo + (int)((32LL * len) / 33);
            } else {
                const int f = __ffs(m) - 1;
                const int new_hi = lo + (int)(((long long)(f + 1) * len) / 33);
                if (f > 0) lo = lo + (int)(((long long)f * len) / 33);
                hi = new_hi;
            }
        }
        // final: hi - lo <= 32, lane probes lo+lane
        const int pos = lo + lane;
        const bool ge = (pos < hi) ? (__ldg(coors + (long long)pos * 4) >= k) : true;
        const unsigned m = __ballot_sync(0xffffffffu, ge);
        const int ans = lo + (__ffs(m) - 1);
        if (lane == 0) g_bound[warp] = ans;
    }
}

// ---------------------------------------------------------------------------
// Norm kernel: LayerNorm(C=64) + FiLM modulation.
// Half-warp (16 lanes) per row, float4 per lane. Each thread handles FOUR
// rows (base, +2, +4, +6) for load-level parallelism. Block covers 64 rows.
// Batch index derived from 7 boundary compares — no coors reads.
// ---------------------------------------------------------------------------
__global__ void __launch_bounds__(256)
norm_mod_kernel(const float* __restrict__ x,
                float* __restrict__ out,
                int n_rows)
{
    __shared__ float sA[B_DIM * C_DIM];
    __shared__ float sB[B_DIM * C_DIM];
    __shared__ int sbnd[B_DIM - 1];

    const int tid = threadIdx.x;
    for (int i = tid; i < B_DIM * C_DIM; i += 256) {
        sA[i] = g_coef[i];
        sB[i] = g_coef[B_DIM * C_DIM + i];
    }
    if (tid < B_DIM - 1) sbnd[tid] = g_bound[tid];
    __syncthreads();

    int bnd[B_DIM - 1];
#pragma unroll
    for (int k = 0; k < B_DIM - 1; ++k) bnd[k] = sbnd[k];

    const int warp = tid >> 5;
    const int lane = tid & 31;
    const int half = lane >> 4;
    const int sub  = lane & 15;

    const long long base = (long long)blockIdx.x * 64 + warp * 8 + half;

    long long rows[4];
    bool ok[4];
    float4 v[4];
#pragma unroll
    for (int r = 0; r < 4; ++r) {
        rows[r] = base + 2 * r;
        ok[r] = rows[r] < n_rows;
        v[r] = ok[r] ? __ldcs(reinterpret_cast<const float4*>(x + rows[r] * C_DIM) + sub)
                     : make_float4(0.f, 0.f, 0.f, 0.f);
    }

    float s[4], s2[4];
#pragma unroll
    for (int r = 0; r < 4; ++r) {
        s[r]  = v[r].x + v[r].y + v[r].z + v[r].w;
        s2[r] = v[r].x * v[r].x + v[r].y * v[r].y + v[r].z * v[r].z + v[r].w * v[r].w;
    }
#pragma unroll
    for (int o = 8; o >= 1; o >>= 1) {
#pragma unroll
        for (int r = 0; r < 4; ++r) {
            s[r]  += __shfl_xor_sync(0xffffffffu, s[r],  o);
            s2[r] += __shfl_xor_sync(0xffffffffu, s2[r], o);
        }
    }

#pragma unroll
    for (int r = 0; r < 4; ++r) {
        if (!ok[r]) continue;
        const float mu  = s[r] * (1.0f / 64.0f);
        const float var = s2[r] * (1.0f / 64.0f) - mu * mu;
        const float rs  = rsqrtf(var + EPS);

        int b = 0;
#pragma unroll
        for (int k = 0; k < B_DIM - 1; ++k) b += (rows[r] >= (long long)bnd[k]);

        const float4 a4 = reinterpret_cast<const float4*>(sA + b * C_DIM)[sub];
        const float4 b4 = reinterpret_cast<const float4*>(sB + b * C_DIM)[sub];
        float4 o4;
        o4.x = (v[r].x - mu) * rs * a4.x + b4.x;
        o4.y = (v[r].y - mu) * rs * a4.y + b4.y;
        o4.z = (v[r].z - mu) * rs * a4.z + b4.z;
        o4.w = (v[r].w - mu) * rs * a4.w + b4.w;
        __stcs(reinterpret_cast<float4*>(out + rows[r] * C_DIM) + sub, o4);
    }
}

// ---------------------------------------------------------------------------
// Launch. Inputs (metadata order): x, dataset_token, gamma, beta, W, b, coors
// ---------------------------------------------------------------------------
extern "C" void kernel_launch(void* const* d_in, const int* in_sizes, int n_in,
                              void* d_out, int out_size)
{
    const float* x      = (const float*)d_in[0];
    const float* token  = (const float*)d_in[1];
    const float* gamma  = (const float*)d_in[2];
    const float* beta   = (const float*)d_in[3];
    const float* W      = (const float*)d_in[4];
    const float* bvec   = (const float*)d_in[5];
    const int*   coors  = (const int*)d_in[6];
    float* out = (float*)d_out;

    const int n_rows = in_sizes[0] / C_DIM;

    setup_kernel<<<65, 256>>>(token, W, bvec, gamma, beta, coors, n_rows);

    const int rows_per_block = 64;
    const int grid = (n_rows + rows_per_block - 1) / rows_per_block;
    norm_mod_kernel<<<grid, 256>>>(x, out, n_rows);
}

// round 5
// speedup vs baseline: 2.7713x; 1.0108x over previous
#include <cuda_runtime.h>

#define EPS 1e-5f
#define C_DIM 64
#define B_DIM 8
#define CTX_DIM 256

// Fused modulation coefficients: [0..511]   = A[b][c] = gamma[c]*(1+scale[b][c])
//                                [512..1023]= B[b][c] = beta[c]*(1+scale[b][c]) + shift[b][c]
__device__ float g_coef[2 * B_DIM * C_DIM];
// g_bound[k] = first row whose batch >= k+1. batch(row) = #{k : bound[k] <= row}
__device__ int g_bound[B_DIM - 1];

// ---------------------------------------------------------------------------
// Setup kernel: blocks 0..63 = tiny MLP (warp per (batch,channel) pair);
// block 64 = warp-parallel 33-way search for the 7 batch boundaries in the
// sorted coors[:,0].
// ---------------------------------------------------------------------------
__global__ void __launch_bounds__(256)
setup_kernel(const float* __restrict__ token,  // [8,256]
             const float* __restrict__ W,      // [128,256]
             const float* __restrict__ bvec,   // [128]
             const float* __restrict__ gamma,  // [64]
             const float* __restrict__ beta,   // [64]
             const int* __restrict__ coors,    // [N,4] int32, col 0 sorted
             int n_rows)
{
    const int warp = threadIdx.x >> 5;
    const int lane = threadIdx.x & 31;

    if (blockIdx.x < 64) {
        const int wg = blockIdx.x * 8 + warp;   // 0..511
        const int j = wg >> 6;                  // batch
        const int c = wg & 63;                  // channel

        const float* trow = token + j * CTX_DIM;
        const float* wsh  = W + c * CTX_DIM;
        const float* wsc  = W + (C_DIM + c) * CTX_DIM;

        float acc_sh = 0.0f, acc_sc = 0.0f;
#pragma unroll
        for (int i = 0; i < 8; ++i) {
            const int k = lane + 32 * i;
            const float v = trow[k];
            const float s = v / (1.0f + expf(-v));
            acc_sh += s * wsh[k];
            acc_sc += s * wsc[k];
        }
#pragma unroll
        for (int o = 16; o >= 1; o >>= 1) {
            acc_sh += __shfl_xor_sync(0xffffffffu, acc_sh, o);
            acc_sc += __shfl_xor_sync(0xffffffffu, acc_sc, o);
        }
        if (lane == 0) {
            const float shift = acc_sh + bvec[c];
            const float scale = acc_sc + bvec[C_DIM + c];
            g_coef[j * C_DIM + c]                 = gamma[c] * (1.0f + scale);
            g_coef[B_DIM * C_DIM + j * C_DIM + c] = beta[c] * (1.0f + scale) + shift;
        }
    } else {
        if (warp >= B_DIM - 1) return;
        const int k = warp + 1;
        int lo = 0, hi = n_rows;

        while (hi - lo > 32) {
            const long long len = hi - lo;
            const int pos = lo + (int)(((long long)(lane + 1) * len) / 33);
            const bool ge = __ldg(coors + (long long)pos * 4) >= k;
            const unsigned m = __ballot_sync(0xffffffffu, ge);
            if (m == 0) {
                lo = lo + (int)((32LL * len) / 33);
            } else {
                const int f = __ffs(m) - 1;
                const int new_hi = lo + (int)(((long long)(f + 1) * len) / 33);
                if (f > 0) lo = lo + (int)(((long long)f * len) / 33);
                hi = new_hi;
            }
        }
        const int pos = lo + lane;
        const bool ge = (pos < hi) ? (__ldg(coors + (long long)pos * 4) >= k) : true;
        const unsigned m = __ballot_sync(0xffffffffu, ge);
        if (lane == 0) g_bound[warp] = lo + (__ffs(m) - 1);
    }
}

// ---------------------------------------------------------------------------
// Norm body: 8 lanes per row, 2 float4 per lane per row, 2 rows per thread.
// Warp covers 8 rows; block (256 thr) covers 64 rows.
// ---------------------------------------------------------------------------
template <bool GUARD>
__device__ __forceinline__ void norm_body(const float* __restrict__ x,
                                          float* __restrict__ out,
                                          int n_rows,
                                          const float* sA, const float* sB,
                                          const int* bnd)
{
    const int tid  = threadIdx.x;
    const int warp = tid >> 5;
    const int lane = tid & 31;
    const int g    = lane >> 3;   // row slot 0..3
    const int sub  = lane & 7;    // lane within row

    const int base = blockIdx.x * 64 + warp * 8 + g;
    const int rows[2] = { base, base + 4 };

    float4 v[2][2];
#pragma unroll
    for (int r = 0; r < 2; ++r) {
        bool ok = !GUARD || rows[r] < n_rows;
        const float4* p = reinterpret_cast<const float4*>(x) + rows[r] * 16;
        v[r][0] = ok ? __ldcs(p + sub)     : make_float4(0.f, 0.f, 0.f, 0.f);
        v[r][1] = ok ? __ldcs(p + sub + 8) : make_float4(0.f, 0.f, 0.f, 0.f);
    }

    float s[2], s2[2];
#pragma unroll
    for (int r = 0; r < 2; ++r) {
        s[r]  = (v[r][0].x + v[r][0].y) + (v[r][0].z + v[r][0].w)
              + (v[r][1].x + v[r][1].y) + (v[r][1].z + v[r][1].w);
        s2[r] = v[r][0].x * v[r][0].x + v[r][0].y * v[r][0].y
              + v[r][0].z * v[r][0].z + v[r][0].w * v[r][0].w
              + v[r][1].x * v[r][1].x + v[r][1].y * v[r][1].y
              + v[r][1].z * v[r][1].z + v[r][1].w * v[r][1].w;
    }
#pragma unroll
    for (int o = 4; o >= 1; o >>= 1) {
#pragma unroll
        for (int r = 0; r < 2; ++r) {
            s[r]  += __shfl_xor_sync(0xffffffffu, s[r],  o);
            s2[r] += __shfl_xor_sync(0xffffffffu, s2[r], o);
        }
    }

#pragma unroll
    for (int r = 0; r < 2; ++r) {
        if (GUARD && rows[r] >= n_rows) continue;
        const float mu  = s[r] * (1.0f / 64.0f);
        const float var = s2[r] * (1.0f / 64.0f) - mu * mu;
        const float rs  = rsqrtf(var + EPS);

        int b = 0;
#pragma unroll
        for (int k = 0; k < B_DIM - 1; ++k) b += (rows[r] >= bnd[k]);

        const float4* a0 = reinterpret_cast<const float4*>(sA + b * C_DIM);
        const float4* b0 = reinterpret_cast<const float4*>(sB + b * C_DIM);
        float4* po = reinterpret_cast<float4*>(out) + rows[r] * 16;
#pragma unroll
        for (int h = 0; h < 2; ++h) {
            const float4 a4 = a0[sub + 8 * h];
            const float4 b4 = b0[sub + 8 * h];
            float4 o4;
            o4.x = (v[r][h].x - mu) * rs * a4.x + b4.x;
            o4.y = (v[r][h].y - mu) * rs * a4.y + b4.y;
            o4.z = (v[r][h].z - mu) * rs * a4.z + b4.z;
            o4.w = (v[r][h].w - mu) * rs * a4.w + b4.w;
            __stcs(po + sub + 8 * h, o4);
        }
    }
}

__global__ void __launch_bounds__(256)
norm_mod_kernel(const float* __restrict__ x,
                float* __restrict__ out,
                int n_rows)
{
    __shared__ float sA[B_DIM * C_DIM];
    __shared__ float sB[B_DIM * C_DIM];
    __shared__ int sbnd[B_DIM - 1];

    const int tid = threadIdx.x;
    for (int i = tid; i < B_DIM * C_DIM; i += 256) {
        sA[i] = g_coef[i];
        sB[i] = g_coef[B_DIM * C_DIM + i];
    }
    if (tid < B_DIM - 1) sbnd[tid] = g_bound[tid];
    __syncthreads();

    int bnd[B_DIM - 1];
#pragma unroll
    for (int k = 0; k < B_DIM - 1; ++k) bnd[k] = sbnd[k];

    if ((blockIdx.x + 1) * 64 <= n_rows) {
        norm_body<false>(x, out, n_rows, sA, sB, bnd);
    } else {
        norm_body<true>(x, out, n_rows, sA, sB, bnd);
    }
}

// ---------------------------------------------------------------------------
// Launch. Inputs (metadata order): x, dataset_token, gamma, beta, W, b, coors
// ---------------------------------------------------------------------------
extern "C" void kernel_launch(void* const* d_in, const int* in_sizes, int n_in,
                              void* d_out, int out_size)
{
    const float* x      = (const float*)d_in[0];
    const float* token  = (const float*)d_in[1];
    const float* gamma  = (const float*)d_in[2];
    const float* beta   = (const float*)d_in[3];
    const float* W      = (const float*)d_in[4];
    const float* bvec   = (const float*)d_in[5];
    const int*   coors  = (const int*)d_in[6];
    float* out = (float*)d_out;

    const int n_rows = in_sizes[0] / C_DIM;

    setup_kernel<<<65, 256>>>(token, W, bvec, gamma, beta, coors, n_rows);

    const int rows_per_block = 64;
    const int grid = (n_rows + rows_per_block - 1) / rows_per_block;
    norm_mod_kernel<<<grid, 256>>>(x, out, n_rows);
}

// round 7
// speedup vs baseline: 2.7842x; 1.0047x over previous
#include <cuda_runtime.h>

#define EPS 1e-5f
#define C_DIM 64
#define B_DIM 8
#define CTX_DIM 256
#define SETUP_BLOCKS 65

// Fused modulation coefficients: [0..511]   = A[b][c] = gamma[c]*(1+scale[b][c])
//                                [512..1023]= B[b][c] = beta[c]*(1+scale[b][c]) + shift[b][c]
__device__ __align__(16) float g_coef[2 * B_DIM * C_DIM];
// g_bound[k] = first row whose batch >= k+1. batch(row) = #{k : bound[k] <= row}
__device__ int g_bound[B_DIM - 1];
// Monotone completion counter: +SETUP_BLOCKS per kernel execution.
__device__ unsigned int g_flag = 0;

// ---------------------------------------------------------------------------
// One fused kernel. Blocks 0..63: tiny MLP (one warp per (batch,channel)).
// Block 64: warp-parallel 33-way boundary search on sorted coors[:,0].
// Blocks 65+: LayerNorm(64) + FiLM. Norm blocks load & reduce x BEFORE
// waiting on the setup flag, so setup latency hides behind their own DRAM
// loads. Coefficients are read with NORMAL coherent loads (never __ldg —
// the data is written in this same launch).
// ---------------------------------------------------------------------------
template <bool GUARD>
__global__ void __launch_bounds__(256, 6)
fused_kernel(const float* __restrict__ x,
             const float* __restrict__ token,  // [8,256]
             const float* __restrict__ W,      // [128,256]
             const float* __restrict__ bvec,   // [128]
             const float* __restrict__ gamma,  // [64]
             const float* __restrict__ beta,   // [64]
             const int* __restrict__ coors,    // [N,4] int32, col 0 sorted
             float* __restrict__ out,
             int n_rows)
{
    __shared__ float sA[B_DIM * C_DIM];
    __shared__ float sB[B_DIM * C_DIM];
    __shared__ int sbnd[B_DIM - 1];

    const int tid  = threadIdx.x;
    const int warp = tid >> 5;
    const int lane = tid & 31;

    if (blockIdx.x < SETUP_BLOCKS) {
        if (blockIdx.x < 64) {
            // ---- MLP: warp wg handles (batch j, channel c) ----
            const int wg = blockIdx.x * 8 + warp;   // 0..511
            const int j = wg >> 6;
            const int c = wg & 63;

            const float* trow = token + j * CTX_DIM;
            const float* wsh  = W + c * CTX_DIM;
            const float* wsc  = W + (C_DIM + c) * CTX_DIM;

            float acc_sh = 0.0f, acc_sc = 0.0f;
#pragma unroll
            for (int i = 0; i < 8; ++i) {
                const int k = lane + 32 * i;
                const float v = trow[k];
                const float s = v / (1.0f + expf(-v));
                acc_sh += s * wsh[k];
                acc_sc += s * wsc[k];
            }
#pragma unroll
            for (int o = 16; o >= 1; o >>= 1) {
                acc_sh += __shfl_xor_sync(0xffffffffu, acc_sh, o);
                acc_sc += __shfl_xor_sync(0xffffffffu, acc_sc, o);
            }
            if (lane == 0) {
                const float shift = acc_sh + bvec[c];
                const float scale = acc_sc + bvec[C_DIM + c];
                g_coef[j * C_DIM + c]                 = gamma[c] * (1.0f + scale);
                g_coef[B_DIM * C_DIM + j * C_DIM + c] = beta[c] * (1.0f + scale) + shift;
            }
        } else if (warp < B_DIM - 1) {
            // ---- Boundary search: warp k finds lower_bound(batch >= k+1) ----
            const int k = warp + 1;
            int lo = 0, hi = n_rows;
            while (hi - lo > 32) {
                const long long len = hi - lo;
                const int pos = lo + (int)(((long long)(lane + 1) * len) / 33);
                const bool ge = coors[(long long)pos * 4] >= k;
                const unsigned m = __ballot_sync(0xffffffffu, ge);
                if (m == 0) {
                    lo = lo + (int)((32LL * len) / 33);
                } else {
                    const int f = __ffs(m) - 1;
                    const int new_hi = lo + (int)(((long long)(f + 1) * len) / 33);
                    if (f > 0) lo = lo + (int)(((long long)f * len) / 33);
                    hi = new_hi;
                }
            }
            const int pos = lo + lane;
            const bool ge = (pos < hi) ? (coors[(long long)pos * 4] >= k) : true;
            const unsigned m = __ballot_sync(0xffffffffu, ge);
            if (lane == 0) g_bound[warp] = lo + (__ffs(m) - 1);
        }
        __syncthreads();
        if (tid == 0) {
            __threadfence();                 // release: coef/bound visible first
            atomicAdd(&g_flag, 1u);
        }
        return;
    }

    // ------------------- Norm role -------------------
    const int nb  = blockIdx.x - SETUP_BLOCKS;
    const int g   = lane >> 3;   // row slot 0..3 within warp
    const int sub = lane & 7;    // lane within row (8 lanes x 8 floats)

    const int base  = nb * 64 + warp * 8 + g;
    const int rows0 = base;
    const int rows1 = base + 4;
    const bool ok0 = !GUARD || rows0 < n_rows;
    const bool ok1 = !GUARD || rows1 < n_rows;

    // Phase 1: stream loads + reduction (independent of setup results).
    const float4 z = make_float4(0.f, 0.f, 0.f, 0.f);
    const float4* p0 = reinterpret_cast<const float4*>(x) + rows0 * 16;
    const float4* p1 = reinterpret_cast<const float4*>(x) + rows1 * 16;
    float4 v00 = ok0 ? __ldcs(p0 + sub)     : z;
    float4 v01 = ok0 ? __ldcs(p0 + sub + 8) : z;
    float4 v10 = ok1 ? __ldcs(p1 + sub)     : z;
    float4 v11 = ok1 ? __ldcs(p1 + sub + 8) : z;

    float s0  = (v00.x + v00.y) + (v00.z + v00.w) + (v01.x + v01.y) + (v01.z + v01.w);
    float s20 = v00.x * v00.x + v00.y * v00.y + v00.z * v00.z + v00.w * v00.w
              + v01.x * v01.x + v01.y * v01.y + v01.z * v01.z + v01.w * v01.w;
    float s1  = (v10.x + v10.y) + (v10.z + v10.w) + (v11.x + v11.y) + (v11.z + v11.w);
    float s21 = v10.x * v10.x + v10.y * v10.y + v10.z * v10.z + v10.w * v10.w
              + v11.x * v11.x + v11.y * v11.y + v11.z * v11.z + v11.w * v11.w;

#pragma unroll
    for (int o = 4; o >= 1; o >>= 1) {
        s0  += __shfl_xor_sync(0xffffffffu, s0,  o);
        s20 += __shfl_xor_sync(0xffffffffu, s20, o);
        s1  += __shfl_xor_sync(0xffffffffu, s1,  o);
        s21 += __shfl_xor_sync(0xffffffffu, s21, o);
    }

    // Phase 2: acquire-gate on setup completion, then stage coefficients.
    if (tid == 0) {
        unsigned f;
        do {
            asm volatile("ld.acquire.gpu.global.u32 %0, [%1];"
                         : "=r"(f) : "l"(&g_flag) : "memory");
        } while (f < SETUP_BLOCKS);
    }
    __syncthreads();

    for (int i = tid; i < B_DIM * C_DIM; i += 256) {
        sA[i] = g_coef[i];
        sB[i] = g_coef[B_DIM * C_DIM + i];
    }
    if (tid < B_DIM - 1) sbnd[tid] = g_bound[tid];
    __syncthreads();

    int bnd[B_DIM - 1];
#pragma unroll
    for (int k = 0; k < B_DIM - 1; ++k) bnd[k] = sbnd[k];

    // Row 0
    if (ok0) {
        const float mu  = s0 * (1.0f / 64.0f);
        const float var = s20 * (1.0f / 64.0f) - mu * mu;
        const float rs  = rsqrtf(var + EPS);
        int b = 0;
#pragma unroll
        for (int k = 0; k < B_DIM - 1; ++k) b += (rows0 >= bnd[k]);
        const float4* a0p = reinterpret_cast<const float4*>(sA + b * C_DIM);
        const float4* b0p = reinterpret_cast<const float4*>(sB + b * C_DIM);
        const float4 a0 = a0p[sub], a1 = a0p[sub + 8];
        const float4 b0 = b0p[sub], b1 = b0p[sub + 8];
        float4* po = reinterpret_cast<float4*>(out) + rows0 * 16;
        float4 o0, o1;
        o0.x = (v00.x - mu) * rs * a0.x + b0.x;
        o0.y = (v00.y - mu) * rs * a0.y + b0.y;
        o0.z = (v00.z - mu) * rs * a0.z + b0.z;
        o0.w = (v00.w - mu) * rs * a0.w + b0.w;
        o1.x = (v01.x - mu) * rs * a1.x + b1.x;
        o1.y = (v01.y - mu) * rs * a1.y + b1.y;
        o1.z = (v01.z - mu) * rs * a1.z + b1.z;
        o1.w = (v01.w - mu) * rs * a1.w + b1.w;
        __stcs(po + sub, o0);
        __stcs(po + sub + 8, o1);
    }
    // Row 1
    if (ok1) {
        const float mu  = s1 * (1.0f / 64.0f);
        const float var = s21 * (1.0f / 64.0f) - mu * mu;
        const float rs  = rsqrtf(var + EPS);
        int b = 0;
#pragma unroll
        for (int k = 0; k < B_DIM - 1; ++k) b += (rows1 >= bnd[k]);
        const float4* a0p = reinterpret_cast<const float4*>(sA + b * C_DIM);
        const float4* b0p = reinterpret_cast<const float4*>(sB + b * C_DIM);
        const float4 a0 = a0p[sub], a1 = a0p[sub + 8];
        const float4 b0 = b0p[sub], b1 = b0p[sub + 8];
        float4* po = reinterpret_cast<float4*>(out) + rows1 * 16;
        float4 o0, o1;
        o0.x = (v10.x - mu) * rs * a0.x + b0.x;
        o0.y = (v10.y - mu) * rs * a0.y + b0.y;
        o0.z = (v10.z - mu) * rs * a0.z + b0.z;
        o0.w = (v10.w - mu) * rs * a0.w + b0.w;
        o1.x = (v11.x - mu) * rs * a1.x + b1.x;
        o1.y = (v11.y - mu) * rs * a1.y + b1.y;
        o1.z = (v11.z - mu) * rs * a1.z + b1.z;
        o1.w = (v11.w - mu) * rs * a1.w + b1.w;
        __stcs(po + sub, o0);
        __stcs(po + sub + 8, o1);
    }
}

// ---------------------------------------------------------------------------
// Launch. Inputs (metadata order): x, dataset_token, gamma, beta, W, b, coors
// ---------------------------------------------------------------------------
extern "C" void kernel_launch(void* const* d_in, const int* in_sizes, int n_in,
                              void* d_out, int out_size)
{
    const float* x      = (const float*)d_in[0];
    const float* token  = (const float*)d_in[1];
    const float* gamma  = (const float*)d_in[2];
    const float* beta   = (const float*)d_in[3];
    const float* W      = (const float*)d_in[4];
    const float* bvec   = (const float*)d_in[5];
    const int*   coors  = (const int*)d_in[6];
    float* out = (float*)d_out;

    const int n_rows = in_sizes[0] / C_DIM;
    const int norm_blocks = (n_rows + 63) / 64;
    const int grid = SETUP_BLOCKS + norm_blocks;

    if (n_rows % 64 == 0) {
        fused_kernel<false><<<grid, 256>>>(x, token, W, bvec, gamma, beta, coors, out, n_rows);
    } else {
        fused_kernel<true><<<grid, 256>>>(x, token, W, bvec, gamma, beta, coors, out, n_rows);
    }
}

// round 8
// speedup vs baseline: 2.7972x; 1.0047x over previous
#include <cuda_runtime.h>

#define EPS 1e-5f
#define C_DIM 64
#define B_DIM 8
#define CTX_DIM 256

// Fused modulation coefficients: [0..511]   = A[b][c] = gamma[c]*(1+scale[b][c])
//                                [512..1023]= B[b][c] = beta[c]*(1+scale[b][c]) + shift[b][c]
__device__ __align__(16) float g_coef[2 * B_DIM * C_DIM];
// g_bound[k] = first row whose batch >= k+1. batch(row) = #{k : bound[k] <= row}
__device__ int g_bound[B_DIM - 1];

// ---------------------------------------------------------------------------
// Setup kernel: blocks 0..63 = tiny MLP (one warp per (batch,channel) pair);
// blocks 64..70 = one block per batch boundary, 257-way block-parallel search
// (3 rounds instead of a warp's 4).
// ---------------------------------------------------------------------------
__global__ void __launch_bounds__(256)
setup_kernel(const float* __restrict__ token,  // [8,256]
             const float* __restrict__ W,      // [128,256]
             const float* __restrict__ bvec,   // [128]
             const float* __restrict__ gamma,  // [64]
             const float* __restrict__ beta,   // [64]
             const int* __restrict__ coors,    // [N,4] int32, col 0 sorted
             int n_rows)
{
    const int tid  = threadIdx.x;
    const int warp = tid >> 5;
    const int lane = tid & 31;

    if (blockIdx.x < 64) {
        // ---- MLP: warp wg handles (batch j, channel c) ----
        const int wg = blockIdx.x * 8 + warp;   // 0..511
        const int j = wg >> 6;
        const int c = wg & 63;

        const float* trow = token + j * CTX_DIM;
        const float* wsh  = W + c * CTX_DIM;
        const float* wsc  = W + (C_DIM + c) * CTX_DIM;

        // Front-batch all 24 loads, then compute.
        float tv[8], wa[8], wb[8];
#pragma unroll
        for (int i = 0; i < 8; ++i) {
            const int k = lane + 32 * i;
            tv[i] = __ldg(trow + k);
            wa[i] = __ldg(wsh + k);
            wb[i] = __ldg(wsc + k);
        }
        float acc_sh = 0.0f, acc_sc = 0.0f;
#pragma unroll
        for (int i = 0; i < 8; ++i) {
            const float s = tv[i] / (1.0f + expf(-tv[i]));
            acc_sh += s * wa[i];
            acc_sc += s * wb[i];
        }
#pragma unroll
        for (int o = 16; o >= 1; o >>= 1) {
            acc_sh += __shfl_xor_sync(0xffffffffu, acc_sh, o);
            acc_sc += __shfl_xor_sync(0xffffffffu, acc_sc, o);
        }
        if (lane == 0) {
            const float shift = acc_sh + bvec[c];
            const float scale = acc_sc + bvec[C_DIM + c];
            g_coef[j * C_DIM + c]                 = gamma[c] * (1.0f + scale);
            g_coef[B_DIM * C_DIM + j * C_DIM + c] = beta[c] * (1.0f + scale) + shift;
        }
    } else {
        // ---- Boundary search: block (64+k-1) finds lower_bound(batch >= k) ----
        // Block-parallel 257-way split: [lo,hi] shrinks by 257x per round.
        __shared__ int s_lo, s_hi;
        const int k = (int)blockIdx.x - 63;      // 1..7
        if (tid == 0) { s_lo = 0; s_hi = n_rows; }
        __syncthreads();

        while (s_hi - s_lo > 256) {
            const int lo = s_lo, hi = s_hi;
            const long long len = hi - lo;
            const int pos = lo + (int)(((long long)(tid + 1) * len) / 257);
            const bool ge = __ldg(coors + (long long)pos * 4) >= k;
            // thread whose probe is the FIRST 'ge' (or detects all-false) updates
            const int posL = lo + (int)(((long long)tid * len) / 257);
            const bool geL = (tid == 0) ? false
                                        : (__ldg(coors + (long long)posL * 4) >= k);
            __syncthreads();
            if (ge && !geL) {            // first transition: answer in (posL? ...] -> [posL_bound, pos]
                s_lo = (tid == 0) ? lo : posL;
                s_hi = pos;
            }
            if (tid == 255 && !ge) {     // all probes false: answer in (pos_last, hi]
                s_lo = pos;
                // s_hi unchanged
            }
            __syncthreads();
        }
        // Final: <=256 candidates, one probe per thread, warp-free reduction via shared.
        __shared__ int s_ans;
        if (tid == 0) s_ans = s_hi;
        __syncthreads();
        const int lo = s_lo, hi = s_hi;
        const int pos = lo + tid;
        if (pos < hi && __ldg(coors + (long long)pos * 4) >= k) {
            atomicMin(&s_ans, pos);
        }
        __syncthreads();
        if (tid == 0) g_bound[k - 1] = s_ans;
    }
}

// ---------------------------------------------------------------------------
// Norm kernel: LayerNorm(C=64) + FiLM. 8 lanes per row, 2 float4 per lane,
// 2 rows per thread; block covers 64 rows. __launch_bounds__(256,6) keeps
// regs <= 40 -> 6 CTAs/SM.
// ---------------------------------------------------------------------------
template <bool GUARD>
__global__ void __launch_bounds__(256, 6)
norm_mod_kernel(const float* __restrict__ x,
                float* __restrict__ out,
                int n_rows)
{
    __shared__ float sA[B_DIM * C_DIM];
    __shared__ float sB[B_DIM * C_DIM];
    __shared__ int sbnd[B_DIM - 1];

    const int tid = threadIdx.x;
    for (int i = tid; i < B_DIM * C_DIM; i += 256) {
        sA[i] = g_coef[i];
        sB[i] = g_coef[B_DIM * C_DIM + i];
    }
    if (tid < B_DIM - 1) sbnd[tid] = g_bound[tid];
    __syncthreads();

    int bnd[B_DIM - 1];
#pragma unroll
    for (int k = 0; k < B_DIM - 1; ++k) bnd[k] = sbnd[k];

    const int warp = tid >> 5;
    const int lane = tid & 31;
    const int g    = lane >> 3;   // row slot 0..3 within warp
    const int sub  = lane & 7;    // lane within row

    const int base  = blockIdx.x * 64 + warp * 8 + g;
    const int rows0 = base;
    const int rows1 = base + 4;
    const bool ok0 = !GUARD || rows0 < n_rows;
    const bool ok1 = !GUARD || rows1 < n_rows;

    const float4 z = make_float4(0.f, 0.f, 0.f, 0.f);
    const float4* p0 = reinterpret_cast<const float4*>(x) + rows0 * 16;
    const float4* p1 = reinterpret_cast<const float4*>(x) + rows1 * 16;
    float4 v00 = ok0 ? __ldcs(p0 + sub)     : z;
    float4 v01 = ok0 ? __ldcs(p0 + sub + 8) : z;
    float4 v10 = ok1 ? __ldcs(p1 + sub)     : z;
    float4 v11 = ok1 ? __ldcs(p1 + sub + 8) : z;

    float s0  = (v00.x + v00.y) + (v00.z + v00.w) + (v01.x + v01.y) + (v01.z + v01.w);
    float s20 = v00.x * v00.x + v00.y * v00.y + v00.z * v00.z + v00.w * v00.w
              + v01.x * v01.x + v01.y * v01.y + v01.z * v01.z + v01.w * v01.w;
    float s1  = (v10.x + v10.y) + (v10.z + v10.w) + (v11.x + v11.y) + (v11.z + v11.w);
    float s21 = v10.x * v10.x + v10.y * v10.y + v10.z * v10.z + v10.w * v10.w
              + v11.x * v11.x + v11.y * v11.y + v11.z * v11.z + v11.w * v11.w;

#pragma unroll
    for (int o = 4; o >= 1; o >>= 1) {
        s0  += __shfl_xor_sync(0xffffffffu, s0,  o);
        s20 += __shfl_xor_sync(0xffffffffu, s20, o);
        s1  += __shfl_xor_sync(0xffffffffu, s1,  o);
        s21 += __shfl_xor_sync(0xffffffffu, s21, o);
    }

    if (ok0) {
        const float mu  = s0 * (1.0f / 64.0f);
        const float var = s20 * (1.0f / 64.0f) - mu * mu;
        const float rs  = rsqrtf(var + EPS);
        int b = 0;
#pragma unroll
        for (int k = 0; k < B_DIM - 1; ++k) b += (rows0 >= bnd[k]);
        const float4* ap = reinterpret_cast<const float4*>(sA + b * C_DIM);
        const float4* bp = reinterpret_cast<const float4*>(sB + b * C_DIM);
        const float4 a0 = ap[sub], a1 = ap[sub + 8];
        const float4 b0 = bp[sub], b1 = bp[sub + 8];
        float4* po = reinterpret_cast<float4*>(out) + rows0 * 16;
        float4 o0, o1;
        o0.x = (v00.x - mu) * rs * a0.x + b0.x;
        o0.y = (v00.y - mu) * rs * a0.y + b0.y;
        o0.z = (v00.z - mu) * rs * a0.z + b0.z;
        o0.w = (v00.w - mu) * rs * a0.w + b0.w;
        o1.x = (v01.x - mu) * rs * a1.x + b1.x;
        o1.y = (v01.y - mu) * rs * a1.y + b1.y;
        o1.z = (v01.z - mu) * rs * a1.z + b1.z;
        o1.w = (v01.w - mu) * rs * a1.w + b1.w;
        __stcs(po + sub, o0);
        __stcs(po + sub + 8, o1);
    }
    if (ok1) {
        const float mu  = s1 * (1.0f / 64.0f);
        const float var = s21 * (1.0f / 64.0f) - mu * mu;
        const float rs  = rsqrtf(var + EPS);
        int b = 0;
#pragma unroll
        for (int k = 0; k < B_DIM - 1; ++k) b += (rows1 >= bnd[k]);
        const float4* ap = reinterpret_cast<const float4*>(sA + b * C_DIM);
        const float4* bp = reinterpret_cast<const float4*>(sB + b * C_DIM);
        const float4 a0 = ap[sub], a1 = ap[sub + 8];
        const float4 b0 = bp[sub], b1 = bp[sub + 8];
        float4* po = reinterpret_cast<float4*>(out) + rows1 * 16;
        float4 o0, o1;
        o0.x = (v10.x - mu) * rs * a0.x + b0.x;
        o0.y = (v10.y - mu) * rs * a0.y + b0.y;
        o0.z = (v10.z - mu) * rs * a0.z + b0.z;
        o0.w = (v10.w - mu) * rs * a0.w + b0.w;
        o1.x = (v11.x - mu) * rs * a1.x + b1.x;
        o1.y = (v11.y - mu) * rs * a1.y + b1.y;
        o1.z = (v11.z - mu) * rs * a1.z + b1.z;
        o1.w = (v11.w - mu) * rs * a1.w + b1.w;
        __stcs(po + sub, o0);
        __stcs(po + sub + 8, o1);
    }
}

// ---------------------------------------------------------------------------
// Launch. Inputs (metadata order): x, dataset_token, gamma, beta, W, b, coors
// ---------------------------------------------------------------------------
extern "C" void kernel_launch(void* const* d_in, const int* in_sizes, int n_in,
                              void* d_out, int out_size)
{
    const float* x      = (const float*)d_in[0];
    const float* token  = (const float*)d_in[1];
    const float* gamma  = (const float*)d_in[2];
    const float* beta   = (const float*)d_in[3];
    const float* W      = (const float*)d_in[4];
    const float* bvec   = (const float*)d_in[5];
    const int*   coors  = (const int*)d_in[6];
    float* out = (float*)d_out;

    const int n_rows = in_sizes[0] / C_DIM;

    setup_kernel<<<64 + (B_DIM - 1), 256>>>(token, W, bvec, gamma, beta, coors, n_rows);

    const int grid = (n_rows + 63) / 64;
    if (n_rows % 64 == 0) {
        norm_mod_kernel<false><<<grid, 256>>>(x, out, n_rows);
    } else {
        norm_mod_kernel<true><<<grid, 256>>>(x, out, n_rows);
    }
}